// round 1
// baseline (speedup 1.0000x reference)
#include <cuda_runtime.h>

#define H_DIM 2048
#define I_DIM 1024
#define NEXP  8
#define T_TOK 2048
#define TOPK  2
#define NSLOT (T_TOK * TOPK)   // 4096

// ---- scratch (static device allocations; no cudaMalloc allowed) ----
__device__ int   d_counts[NEXP];
__device__ int   d_list[NEXP * NSLOT];
__device__ int   d_use32;
__device__ float d_act[(size_t)NSLOT * I_DIM];    // 16 MB: silu(g)*u*w per slot
__device__ float d_part[(size_t)NSLOT * H_DIM];   // 32 MB: per-slot down output

// ---------------------------------------------------------------------------
// Prep: zero counts + detect whether expert_indices is int32 or int64.
// If int64, the high 32-bit word of every element is 0 (values are 0..7).
// If int32, odd-position words are random 0..7 -> some nonzero almost surely.
// Reading words [0, 4096) is safe under either interpretation.
// ---------------------------------------------------------------------------
__global__ void k_prep(const int* __restrict__ idx32) {
    __shared__ int found;
    if (threadIdx.x == 0) found = 0;
    if (threadIdx.x < NEXP) d_counts[threadIdx.x] = 0;
    __syncthreads();
    int f = 0;
    for (int i = threadIdx.x; i < T_TOK; i += blockDim.x)
        if (idx32[2 * i + 1] != 0) f = 1;
    if (f) atomicOr(&found, 1);
    __syncthreads();
    if (threadIdx.x == 0) d_use32 = found;
}

__global__ void k_route(const int* __restrict__ idx32) {
    int s = blockIdx.x * 256 + threadIdx.x;
    if (s < NSLOT) {
        int e = d_use32 ? idx32[s] : idx32[2 * s];
        int p = atomicAdd(&d_counts[e], 1);
        d_list[e * NSLOT + p] = s;
    }
}

// ---------------------------------------------------------------------------
// GEMM 1: for each expert, A = gathered x rows [Me, 2048],
// B = gate[e], up[e] (both [1024, 2048], K-major)  ->  act[slot, 0:1024]
// Tiles: 64(M) x 64(N) x 16(K), 256 threads, 4x4 microtile, fused epilogue.
// ---------------------------------------------------------------------------
__global__ __launch_bounds__(256, 2) void k_gateup(
    const float* __restrict__ x, const float* __restrict__ gate,
    const float* __restrict__ up, const float* __restrict__ wts) {

    const int e   = blockIdx.z;
    const int cnt = d_counts[e];
    const int m0  = blockIdx.x * 64;          // x-major = M so L2 shares B tiles
    if (m0 >= cnt) return;
    const int n0  = blockIdx.y * 64;

    __shared__ float As[16][64];
    __shared__ float Bg[16][64];
    __shared__ float Bu[16][64];
    __shared__ int   Srow[64];

    const int tid = threadIdx.x;
    const int tx  = tid & 15;
    const int ty  = tid >> 4;

    if (tid < 64) {
        int m = m0 + tid;
        Srow[tid] = (m < cnt) ? d_list[e * NSLOT + m] : d_list[e * NSLOT + m0];
    }
    __syncthreads();

    const int lr = tid >> 2;          // 0..63  tile row
    const int lc = (tid & 3) * 4;     // 0,4,8,12 k offset

    const int tok = Srow[lr] >> 1;    // slot -> token
    const float* aptr = x    + (size_t)tok * H_DIM + lc;
    const float* gptr = gate + ((size_t)e * I_DIM + n0 + lr) * H_DIM + lc;
    const float* uptr = up   + ((size_t)e * I_DIM + n0 + lr) * H_DIM + lc;

    float accg[4][4] = {};
    float accu[4][4] = {};

    for (int kb = 0; kb < H_DIM; kb += 16) {
        float4 av = *(const float4*)(aptr + kb);
        float4 gv = *(const float4*)(gptr + kb);
        float4 uv = *(const float4*)(uptr + kb);
        __syncthreads();
        As[lc + 0][lr] = av.x; As[lc + 1][lr] = av.y;
        As[lc + 2][lr] = av.z; As[lc + 3][lr] = av.w;
        Bg[lc + 0][lr] = gv.x; Bg[lc + 1][lr] = gv.y;
        Bg[lc + 2][lr] = gv.z; Bg[lc + 3][lr] = gv.w;
        Bu[lc + 0][lr] = uv.x; Bu[lc + 1][lr] = uv.y;
        Bu[lc + 2][lr] = uv.z; Bu[lc + 3][lr] = uv.w;
        __syncthreads();
#pragma unroll
        for (int kk = 0; kk < 16; kk++) {
            float a[4], bg[4], bu[4];
            *(float4*)a  = *(const float4*)&As[kk][ty * 4];
            *(float4*)bg = *(const float4*)&Bg[kk][tx * 4];
            *(float4*)bu = *(const float4*)&Bu[kk][tx * 4];
#pragma unroll
            for (int i = 0; i < 4; i++)
#pragma unroll
                for (int j = 0; j < 4; j++) {
                    accg[i][j] += a[i] * bg[j];
                    accu[i][j] += a[i] * bu[j];
                }
        }
    }

#pragma unroll
    for (int i = 0; i < 4; i++) {
        int m = m0 + ty * 4 + i;
        if (m < cnt) {
            int   slot = Srow[ty * 4 + i];
            float w    = wts[slot];
            float* dst = d_act + (size_t)slot * I_DIM + n0 + tx * 4;
#pragma unroll
            for (int j = 0; j < 4; j++) {
                float g  = accg[i][j];
                float sg = g / (1.0f + __expf(-g));   // silu
                dst[j] = sg * accu[i][j] * w;
            }
        }
    }
}

// ---------------------------------------------------------------------------
// GEMM 2: for each expert, A = act rows [Me, 1024], B = down[e] [2048, 1024]
// -> d_part[slot, 0:2048]
// ---------------------------------------------------------------------------
__global__ __launch_bounds__(256, 2) void k_down(const float* __restrict__ down) {
    const int e   = blockIdx.z;
    const int cnt = d_counts[e];
    const int m0  = blockIdx.x * 64;
    if (m0 >= cnt) return;
    const int n0  = blockIdx.y * 64;

    __shared__ float As[16][64];
    __shared__ float Bs[16][64];
    __shared__ int   Srow[64];

    const int tid = threadIdx.x;
    const int tx  = tid & 15;
    const int ty  = tid >> 4;

    if (tid < 64) {
        int m = m0 + tid;
        Srow[tid] = (m < cnt) ? d_list[e * NSLOT + m] : d_list[e * NSLOT + m0];
    }
    __syncthreads();

    const int lr = tid >> 2;
    const int lc = (tid & 3) * 4;

    const float* aptr = d_act + (size_t)Srow[lr] * I_DIM + lc;
    const float* bptr = down  + ((size_t)e * H_DIM + n0 + lr) * I_DIM + lc;

    float acc[4][4] = {};

    for (int kb = 0; kb < I_DIM; kb += 16) {
        float4 av = *(const float4*)(aptr + kb);
        float4 bv = *(const float4*)(bptr + kb);
        __syncthreads();
        As[lc + 0][lr] = av.x; As[lc + 1][lr] = av.y;
        As[lc + 2][lr] = av.z; As[lc + 3][lr] = av.w;
        Bs[lc + 0][lr] = bv.x; Bs[lc + 1][lr] = bv.y;
        Bs[lc + 2][lr] = bv.z; Bs[lc + 3][lr] = bv.w;
        __syncthreads();
#pragma unroll
        for (int kk = 0; kk < 16; kk++) {
            float a[4], b[4];
            *(float4*)a = *(const float4*)&As[kk][ty * 4];
            *(float4*)b = *(const float4*)&Bs[kk][tx * 4];
#pragma unroll
            for (int i = 0; i < 4; i++)
#pragma unroll
                for (int j = 0; j < 4; j++)
                    acc[i][j] += a[i] * b[j];
        }
    }

#pragma unroll
    for (int i = 0; i < 4; i++) {
        int m = m0 + ty * 4 + i;
        if (m < cnt) {
            int    slot = Srow[ty * 4 + i];
            float* dst  = d_part + (size_t)slot * H_DIM + n0 + tx * 4;
#pragma unroll
            for (int j = 0; j < 4; j++) dst[j] = acc[i][j];
        }
    }
}

// ---------------------------------------------------------------------------
// Reduce: out[t,h] = part[2t,h] + part[2t+1,h]   (both slots always written)
// ---------------------------------------------------------------------------
__global__ void k_reduce(float* __restrict__ out) {
    int p = blockIdx.x * 256 + threadIdx.x;          // float4 index
    const int HV = H_DIM / 4;
    if (p < T_TOK * HV) {
        int t  = p / HV;
        int h4 = p - t * HV;
        const float4* P = (const float4*)d_part;
        float4 a = P[(size_t)(2 * t)     * HV + h4];
        float4 b = P[(size_t)(2 * t + 1) * HV + h4];
        float4 r;
        r.x = a.x + b.x; r.y = a.y + b.y; r.z = a.z + b.z; r.w = a.w + b.w;
        ((float4*)out)[p] = r;
    }
}

// ---------------------------------------------------------------------------
extern "C" void kernel_launch(void* const* d_in, const int* in_sizes, int n_in,
                              void* d_out, int out_size) {
    const float* x    = (const float*)d_in[0];
    const int*   idx  = (const int*)  d_in[1];   // int32 view; width auto-detected
    const float* wts  = (const float*)d_in[2];
    const float* gate = (const float*)d_in[3];
    const float* up   = (const float*)d_in[4];
    const float* down = (const float*)d_in[5];
    float*       out  = (float*)d_out;

    k_prep<<<1, 1024>>>(idx);
    k_route<<<NSLOT / 256, 256>>>(idx);

    dim3 g1(64, I_DIM / 64, NEXP);    // x = M-tiles (worst case 4096/64), y = N-tiles
    k_gateup<<<g1, 256>>>(x, gate, up, wts);

    dim3 g2(64, H_DIM / 64, NEXP);
    k_down<<<g2, 256>>>(down);

    k_reduce<<<(T_TOK * (H_DIM / 4) + 255) / 256, 256>>>(out);
}

// round 3
// speedup vs baseline: 3.4354x; 3.4354x over previous
#include <cuda_runtime.h>
#include <cstdint>

#define H_DIM 2048
#define I_DIM 1024
#define NEXP  8
#define T_TOK 2048
#define NSLOT 4096   // T_TOK * TOPK

// ---------------- static device scratch -------------------------------------
__device__ int   d_counts[NEXP];
__device__ int   d_list[NEXP * NSLOT];
__device__ int   d_use32;
__device__ float d_act[(size_t)NSLOT * I_DIM];    // 16 MB  (tf32-rounded)
__device__ float d_part[(size_t)NSLOT * H_DIM];   // 32 MB

// ---------------- portable PTX helpers (no 'a'-gated instructions) ----------
__device__ __forceinline__ uint32_t smem_u32(const void* p) {
    uint32_t a;
    asm("{ .reg .u64 t; cvta.to.shared.u64 t, %1; cvt.u32.u64 %0, t; }"
        : "=r"(a) : "l"(p));
    return a;
}
__device__ __forceinline__ void cp16(uint32_t dst, const void* src) {
    asm volatile("cp.async.cg.shared.global [%0], [%1], 16;"
                 :: "r"(dst), "l"(src) : "memory");
}
#define CP_COMMIT() asm volatile("cp.async.commit_group;" ::: "memory")
#define CP_WAIT0()  asm volatile("cp.async.wait_group 0;" ::: "memory")
#define CP_WAIT1()  asm volatile("cp.async.wait_group 1;" ::: "memory")

__device__ __forceinline__ void mma_tf32(float* c, const uint32_t* a, const uint32_t* b) {
    asm volatile("mma.sync.aligned.m16n8k8.row.col.f32.tf32.tf32.f32 "
                 "{%0,%1,%2,%3}, {%4,%5,%6,%7}, {%8,%9}, {%0,%1,%2,%3};"
                 : "+f"(c[0]), "+f"(c[1]), "+f"(c[2]), "+f"(c[3])
                 : "r"(a[0]), "r"(a[1]), "r"(a[2]), "r"(a[3]),
                   "r"(b[0]), "r"(b[1]));
}
__device__ __forceinline__ uint32_t rna(uint32_t bits) {
    uint32_t u;
    asm("cvt.rna.tf32.f32 %0, %1;" : "=r"(u) : "f"(__uint_as_float(bits)));
    return u;
}
__device__ __forceinline__ float rnaf(float f) {
    uint32_t u;
    asm("cvt.rna.tf32.f32 %0, %1;" : "=r"(u) : "f"(f));
    return __uint_as_float(u);
}

// ---------------- routing ---------------------------------------------------
__global__ void k_prep(const int* __restrict__ idx32) {
    __shared__ int found;
    if (threadIdx.x == 0) found = 0;
    if (threadIdx.x < NEXP) d_counts[threadIdx.x] = 0;
    __syncthreads();
    int f = 0;
    for (int i = threadIdx.x; i < T_TOK; i += blockDim.x)
        if (idx32[2 * i + 1] != 0) f = 1;
    if (f) atomicOr(&found, 1);
    __syncthreads();
    if (threadIdx.x == 0) d_use32 = found;
}
__global__ void k_route(const int* __restrict__ idx32) {
    int s = blockIdx.x * 256 + threadIdx.x;
    if (s < NSLOT) {
        int e = d_use32 ? idx32[s] : idx32[2 * s];
        int p = atomicAdd(&d_counts[e], 1);
        d_list[e * NSLOT + p] = s;
    }
}

// ============================================================================
// GEMM1: gate+up fused.  CTA tile 128(M)x128(N), BK=32, 3-stage cp.async ring.
// smem tile layout: row r (128B = 8 granules of 16B), granule g stored at
// byte r*128 + (g ^ (r&7))*16  -> conflict-free LDS.32 fragment fetches.
// ============================================================================
#define TILE_B   16384              // 128 rows * 128 bytes
#define G1_STAGE (3 * TILE_B)       // A, G, U
#define G1_SMEM  (512 + 3 * G1_STAGE)
#define G2_STAGE (2 * TILE_B)       // A, B
#define G2_SMEM  (512 + 3 * G2_STAGE)

__global__ __launch_bounds__(256, 1) void k_gu(
    const float* __restrict__ x, const float* __restrict__ gate,
    const float* __restrict__ up, const float* __restrict__ wts) {

    extern __shared__ char smem[];
    const int e   = blockIdx.z;
    const int cnt = d_counts[e];
    const int m0  = blockIdx.x * 128;
    if (m0 >= cnt) return;
    const int n0  = blockIdx.y * 128;
    const int tid = threadIdx.x;

    int* Srow = (int*)smem;
    if (tid < 128) {
        int m = m0 + tid;
        Srow[tid] = d_list[e * NSLOT + (m < cnt ? m : m0)];
    }
    __syncthreads();

    const uint32_t sb = smem_u32(smem);

    // ---- cp.async source/dest mapping: thread -> row tid/2, 4 granules ----
    const int r    = tid >> 1;
    const int cgrp = tid & 1;                       // which half of the row
    const float* aP = x    + (size_t)(Srow[r] >> 1) * H_DIM + cgrp * 16;
    const float* gP = gate + ((size_t)e * I_DIM + n0 + r) * H_DIM + cgrp * 16;
    const float* uP = up   + ((size_t)e * I_DIM + n0 + r) * H_DIM + cgrp * 16;
    uint32_t dA[4], dG[4], dU[4];
#pragma unroll
    for (int j = 0; j < 4; j++) {
        uint32_t gsw = (uint32_t)((cgrp * 4 + j) ^ (r & 7));
        uint32_t o   = (uint32_t)r * 128 + gsw * 16;
        dA[j] = o; dG[j] = TILE_B + o; dU[j] = 2 * TILE_B + o;
    }

    const int lane = tid & 31, wid = tid >> 5;
    const int wm = wid & 1, wn = wid >> 1;
    const int lr = lane >> 2, lc = lane & 3;
    const int rowA = wm * 64 + lr;
    const int rowB = wn * 32 + lr;

    float Cg[4][4][4] = {}, Cu[4][4][4] = {};

    const int NIT = H_DIM / 32;

    // prologue: stages 0,1
#pragma unroll
    for (int pit = 0; pit < 2; pit++) {
        uint32_t base = sb + 512 + pit * G1_STAGE;
        int kb = pit * 32;
#pragma unroll
        for (int j = 0; j < 4; j++) {
            cp16(base + dA[j], aP + kb + j * 4);
            cp16(base + dG[j], gP + kb + j * 4);
            cp16(base + dU[j], uP + kb + j * 4);
        }
        CP_COMMIT();
    }

    int buf = 0;
    for (int it = 0; it < NIT; ++it) {
        if (it < NIT - 1) CP_WAIT1(); else CP_WAIT0();
        __syncthreads();

        const char* bA = smem + 512 + buf * G1_STAGE;
        const char* bG = bA + TILE_B;
        const char* bU = bG + TILE_B;
#pragma unroll
        for (int ck = 0; ck < 4; ck++) {
            const int g0 = (2 * ck) ^ lr;
            const int g1 = g0 ^ 1;
            uint32_t a[4][4];
#pragma unroll
            for (int mf = 0; mf < 4; mf++) {
                const char* p = bA + (rowA + mf * 16) * 128 + lc * 4;
                a[mf][0] = rna(*(const uint32_t*)(p + g0 * 16));
                a[mf][1] = rna(*(const uint32_t*)(p + 1024 + g0 * 16));
                a[mf][2] = rna(*(const uint32_t*)(p + g1 * 16));
                a[mf][3] = rna(*(const uint32_t*)(p + 1024 + g1 * 16));
            }
            uint32_t bg[4][2], bu[4][2];
#pragma unroll
            for (int nf = 0; nf < 4; nf++) {
                const char* pg = bG + (rowB + nf * 8) * 128 + lc * 4;
                const char* pu = bU + (rowB + nf * 8) * 128 + lc * 4;
                bg[nf][0] = rna(*(const uint32_t*)(pg + g0 * 16));
                bg[nf][1] = rna(*(const uint32_t*)(pg + g1 * 16));
                bu[nf][0] = rna(*(const uint32_t*)(pu + g0 * 16));
                bu[nf][1] = rna(*(const uint32_t*)(pu + g1 * 16));
            }
#pragma unroll
            for (int mf = 0; mf < 4; mf++)
#pragma unroll
                for (int nf = 0; nf < 4; nf++) {
                    mma_tf32(Cg[mf][nf], a[mf], bg[nf]);
                    mma_tf32(Cu[mf][nf], a[mf], bu[nf]);
                }
        }
        __syncthreads();

        if (it + 2 < NIT) {
            uint32_t base = sb + 512 + ((it + 2) % 3) * G1_STAGE;
            int kb = (it + 2) * 32;
#pragma unroll
            for (int j = 0; j < 4; j++) {
                cp16(base + dA[j], aP + kb + j * 4);
                cp16(base + dG[j], gP + kb + j * 4);
                cp16(base + dU[j], uP + kb + j * 4);
            }
            CP_COMMIT();
        }
        buf = (buf + 1 == 3) ? 0 : buf + 1;
    }

    // ---- epilogue: silu(g)*u*w -> d_act, tf32-rounded ----
#pragma unroll
    for (int mf = 0; mf < 4; mf++) {
#pragma unroll
        for (int h = 0; h < 2; h++) {
            int mrow = wm * 64 + mf * 16 + lr + h * 8;
            bool ok  = (m0 + mrow) < cnt;
            int slot = Srow[mrow];
            float w  = ok ? wts[slot] : 0.0f;
            float* dst = d_act + (size_t)slot * I_DIM + n0 + wn * 32 + 2 * lc;
            if (ok) {
#pragma unroll
                for (int nf = 0; nf < 4; nf++) {
                    float g0v = Cg[mf][nf][2 * h],     u0v = Cu[mf][nf][2 * h];
                    float g1v = Cg[mf][nf][2 * h + 1], u1v = Cu[mf][nf][2 * h + 1];
                    float2 o;
                    o.x = rnaf((g0v / (1.0f + __expf(-g0v))) * u0v * w);
                    o.y = rnaf((g1v / (1.0f + __expf(-g1v))) * u1v * w);
                    *(float2*)(dst + nf * 8) = o;
                }
            }
        }
    }
}

// ============================================================================
// GEMM2: down.  Same template, single B, K = I_DIM.
// ============================================================================
__global__ __launch_bounds__(256, 1) void k_dn(const float* __restrict__ down) {
    extern __shared__ char smem[];
    const int e   = blockIdx.z;
    const int cnt = d_counts[e];
    const int m0  = blockIdx.x * 128;
    if (m0 >= cnt) return;
    const int n0  = blockIdx.y * 128;
    const int tid = threadIdx.x;

    int* Srow = (int*)smem;
    if (tid < 128) {
        int m = m0 + tid;
        Srow[tid] = d_list[e * NSLOT + (m < cnt ? m : m0)];
    }
    __syncthreads();

    const uint32_t sb = smem_u32(smem);

    const int r    = tid >> 1;
    const int cgrp = tid & 1;
    const float* aP = d_act + (size_t)Srow[r] * I_DIM + cgrp * 16;
    const float* bP = down  + ((size_t)e * H_DIM + n0 + r) * I_DIM + cgrp * 16;
    uint32_t dA[4], dB[4];
#pragma unroll
    for (int j = 0; j < 4; j++) {
        uint32_t gsw = (uint32_t)((cgrp * 4 + j) ^ (r & 7));
        uint32_t o   = (uint32_t)r * 128 + gsw * 16;
        dA[j] = o; dB[j] = TILE_B + o;
    }

    const int lane = tid & 31, wid = tid >> 5;
    const int wm = wid & 1, wn = wid >> 1;
    const int lr = lane >> 2, lc = lane & 3;
    const int rowA = wm * 64 + lr;
    const int rowB = wn * 32 + lr;

    float C[4][4][4] = {};
    const int NIT = I_DIM / 32;

#pragma unroll
    for (int pit = 0; pit < 2; pit++) {
        uint32_t base = sb + 512 + pit * G2_STAGE;
        int kb = pit * 32;
#pragma unroll
        for (int j = 0; j < 4; j++) {
            cp16(base + dA[j], aP + kb + j * 4);
            cp16(base + dB[j], bP + kb + j * 4);
        }
        CP_COMMIT();
    }

    int buf = 0;
    for (int it = 0; it < NIT; ++it) {
        if (it < NIT - 1) CP_WAIT1(); else CP_WAIT0();
        __syncthreads();

        const char* bA = smem + 512 + buf * G2_STAGE;
        const char* bB = bA + TILE_B;
#pragma unroll
        for (int ck = 0; ck < 4; ck++) {
            const int g0 = (2 * ck) ^ lr;
            const int g1 = g0 ^ 1;
            uint32_t a[4][4];
#pragma unroll
            for (int mf = 0; mf < 4; mf++) {
                const char* p = bA + (rowA + mf * 16) * 128 + lc * 4;
                a[mf][0] = *(const uint32_t*)(p + g0 * 16);         // act pre-rounded
                a[mf][1] = *(const uint32_t*)(p + 1024 + g0 * 16);
                a[mf][2] = *(const uint32_t*)(p + g1 * 16);
                a[mf][3] = *(const uint32_t*)(p + 1024 + g1 * 16);
            }
            uint32_t b[4][2];
#pragma unroll
            for (int nf = 0; nf < 4; nf++) {
                const char* pb = bB + (rowB + nf * 8) * 128 + lc * 4;
                b[nf][0] = rna(*(const uint32_t*)(pb + g0 * 16));
                b[nf][1] = rna(*(const uint32_t*)(pb + g1 * 16));
            }
#pragma unroll
            for (int mf = 0; mf < 4; mf++)
#pragma unroll
                for (int nf = 0; nf < 4; nf++)
                    mma_tf32(C[mf][nf], a[mf], b[nf]);
        }
        __syncthreads();

        if (it + 2 < NIT) {
            uint32_t base = sb + 512 + ((it + 2) % 3) * G2_STAGE;
            int kb = (it + 2) * 32;
#pragma unroll
            for (int j = 0; j < 4; j++) {
                cp16(base + dA[j], aP + kb + j * 4);
                cp16(base + dB[j], bP + kb + j * 4);
            }
            CP_COMMIT();
        }
        buf = (buf + 1 == 3) ? 0 : buf + 1;
    }

#pragma unroll
    for (int mf = 0; mf < 4; mf++) {
#pragma unroll
        for (int h = 0; h < 2; h++) {
            int mrow = wm * 64 + mf * 16 + lr + h * 8;
            bool ok  = (m0 + mrow) < cnt;
            int slot = Srow[mrow];
            float* dst = d_part + (size_t)slot * H_DIM + n0 + wn * 32 + 2 * lc;
            if (ok) {
#pragma unroll
                for (int nf = 0; nf < 4; nf++) {
                    float2 o;
                    o.x = C[mf][nf][2 * h];
                    o.y = C[mf][nf][2 * h + 1];
                    *(float2*)(dst + nf * 8) = o;
                }
            }
        }
    }
}

// ---------------- reduce -----------------------------------------------------
__global__ void k_reduce(float* __restrict__ out) {
    int p = blockIdx.x * 256 + threadIdx.x;
    const int HV = H_DIM / 4;
    if (p < T_TOK * HV) {
        int t  = p / HV;
        int h4 = p - t * HV;
        const float4* P = (const float4*)d_part;
        float4 a = P[(size_t)(2 * t) * HV + h4];
        float4 b = P[(size_t)(2 * t + 1) * HV + h4];
        float4 r;
        r.x = a.x + b.x; r.y = a.y + b.y; r.z = a.z + b.z; r.w = a.w + b.w;
        ((float4*)out)[p] = r;
    }
}

// ---------------- launch -----------------------------------------------------
extern "C" void kernel_launch(void* const* d_in, const int* in_sizes, int n_in,
                              void* d_out, int out_size) {
    const float* x    = (const float*)d_in[0];
    const int*   idx  = (const int*)  d_in[1];
    const float* wts  = (const float*)d_in[2];
    const float* gate = (const float*)d_in[3];
    const float* up   = (const float*)d_in[4];
    const float* down = (const float*)d_in[5];
    float*       out  = (float*)d_out;

    cudaFuncSetAttribute(k_gu, cudaFuncAttributeMaxDynamicSharedMemorySize, G1_SMEM);
    cudaFuncSetAttribute(k_dn, cudaFuncAttributeMaxDynamicSharedMemorySize, G2_SMEM);

    k_prep<<<1, 1024>>>(idx);
    k_route<<<NSLOT / 256, 256>>>(idx);

    dim3 g1(NSLOT / 128, I_DIM / 128, NEXP);   // m-tile fastest -> B reuse in L2
    k_gu<<<g1, 256, G1_SMEM>>>(x, gate, up, wts);

    dim3 g2(NSLOT / 128, H_DIM / 128, NEXP);
    k_dn<<<g2, 256, G2_SMEM>>>(down);

    k_reduce<<<(T_TOK * (H_DIM / 4) + 255) / 256, 256>>>(out);
}

// round 4
// speedup vs baseline: 5.6586x; 1.6471x over previous
#include <cuda_runtime.h>
#include <cstdint>

#define H_DIM 2048
#define I_DIM 1024
#define NEXP  8
#define T_TOK 2048
#define NSLOT 4096   // T_TOK * TOPK

// ---------------- static device scratch -------------------------------------
__device__ int   d_counts[NEXP];
__device__ int   d_list[NEXP * NSLOT];
__device__ int   d_use32;
__device__ float d_act[(size_t)NSLOT * I_DIM];    // 16 MB (tf32-rounded)
__device__ float d_xr[(size_t)T_TOK * H_DIM];     // 16 MB x, tf32-rounded

// ---------------- portable PTX helpers --------------------------------------
__device__ __forceinline__ uint32_t smem_u32(const void* p) {
    uint32_t a;
    asm("{ .reg .u64 t; cvta.to.shared.u64 t, %1; cvt.u32.u64 %0, t; }"
        : "=r"(a) : "l"(p));
    return a;
}
__device__ __forceinline__ void cp16(uint32_t dst, const void* src) {
    asm volatile("cp.async.cg.shared.global [%0], [%1], 16;"
                 :: "r"(dst), "l"(src) : "memory");
}
#define CP_COMMIT() asm volatile("cp.async.commit_group;" ::: "memory")
#define CP_WAIT0()  asm volatile("cp.async.wait_group 0;" ::: "memory")
#define CP_WAIT1()  asm volatile("cp.async.wait_group 1;" ::: "memory")

__device__ __forceinline__ void ldsm4(uint32_t* r, uint32_t addr) {
    asm volatile("ldmatrix.sync.aligned.m8n8.x4.shared.b16 {%0,%1,%2,%3}, [%4];"
                 : "=r"(r[0]), "=r"(r[1]), "=r"(r[2]), "=r"(r[3]) : "r"(addr));
}
__device__ __forceinline__ void mma_tf32(float* c, const uint32_t* a, const uint32_t* b) {
    asm volatile("mma.sync.aligned.m16n8k8.row.col.f32.tf32.tf32.f32 "
                 "{%0,%1,%2,%3}, {%4,%5,%6,%7}, {%8,%9}, {%0,%1,%2,%3};"
                 : "+f"(c[0]), "+f"(c[1]), "+f"(c[2]), "+f"(c[3])
                 : "r"(a[0]), "r"(a[1]), "r"(a[2]), "r"(a[3]),
                   "r"(b[0]), "r"(b[1]));
}
__device__ __forceinline__ uint32_t rna(uint32_t bits) {
    uint32_t u;
    asm("cvt.rna.tf32.f32 %0, %1;" : "=r"(u) : "f"(__uint_as_float(bits)));
    return u;
}
__device__ __forceinline__ float rnaf(float f) {
    uint32_t u;
    asm("cvt.rna.tf32.f32 %0, %1;" : "=r"(u) : "f"(f));
    return __uint_as_float(u);
}
__device__ __forceinline__ void redadd(float* p, float v) {
    asm volatile("red.global.add.f32 [%0], %1;" :: "l"(p), "f"(v) : "memory");
}

// ---------------- routing ---------------------------------------------------
__global__ void k_prep(const int* __restrict__ idx32) {
    __shared__ int found;
    if (threadIdx.x == 0) found = 0;
    if (threadIdx.x < NEXP) d_counts[threadIdx.x] = 0;
    __syncthreads();
    int f = 0;
    for (int i = threadIdx.x; i < T_TOK; i += blockDim.x)
        if (idx32[2 * i + 1] != 0) f = 1;
    if (f) atomicOr(&found, 1);
    __syncthreads();
    if (threadIdx.x == 0) d_use32 = found;
}
__global__ void k_route(const int* __restrict__ idx32) {
    int s = blockIdx.x * 256 + threadIdx.x;
    if (s < NSLOT) {
        int e = d_use32 ? idx32[s] : idx32[2 * s];
        int p = atomicAdd(&d_counts[e], 1);
        d_list[e * NSLOT + p] = s;
    }
}
__global__ void k_cvtx(const float4* __restrict__ s, float4* __restrict__ d, int n4) {
    int i = blockIdx.x * blockDim.x + threadIdx.x;
    if (i < n4) {
        float4 v = s[i];
        float4 o;
        o.x = rnaf(v.x); o.y = rnaf(v.y); o.z = rnaf(v.z); o.w = rnaf(v.w);
        d[i] = o;
    }
}
__global__ void k_zero(float4* __restrict__ o, int n4) {
    int i = blockIdx.x * blockDim.x + threadIdx.x;
    if (i < n4) o[i] = make_float4(0.f, 0.f, 0.f, 0.f);
}

// ============================================================================
// Shared tiling: CTA 128x128, BK=32 (128B rows), swizzle granule g^(row&7).
// ldmatrix lane mapping: li = lane>>3 (matrix), lj = lane&7 (row in matrix).
// A x4: m0=(rows+0,d0) m1=(rows+8,d0) m2=(rows+0,d1) m3=(rows+8,d1)
//   -> row += (li&1)*8, delta16 = (li>>1)*16   (matches a0..a3 order)
// B x4 (pair p): m0=b[2p][0] m1=b[2p][1] m2=b[2p+1][0] m3=b[2p+1][1]
//   -> row += (li>>1)*8, delta16 = (li&1)*16
// address = tile + row*128 + (((ck*32)|delta16) ^ (lj*16))
// ============================================================================
#define TILE_B   16384
#define G1_STAGE (3 * TILE_B)
#define G1_SMEM  (512 + 3 * G1_STAGE)
#define G2_STAGE (2 * TILE_B)
#define G2_SMEM  (512 + 3 * G2_STAGE)

__global__ __launch_bounds__(256, 1) void k_gu(
    const float* __restrict__ gate, const float* __restrict__ up,
    const float* __restrict__ wts) {

    extern __shared__ char smem[];
    const int e   = blockIdx.z;
    const int cnt = d_counts[e];
    const int m0  = blockIdx.x * 128;
    if (m0 >= cnt) return;
    const int n0  = blockIdx.y * 128;
    const int tid = threadIdx.x;

    int* Srow = (int*)smem;
    if (tid < 128) {
        int m = m0 + tid;
        Srow[tid] = d_list[e * NSLOT + (m < cnt ? m : m0)];
    }
    __syncthreads();

    const uint32_t sb = smem_u32(smem);

    // cp.async: thread -> row tid/2, half (tid&1), 4 granules
    const int r    = tid >> 1;
    const int cgrp = tid & 1;
    const float* aP = d_xr + (size_t)(Srow[r] >> 1) * H_DIM + cgrp * 16;
    const float* gP = gate + ((size_t)e * I_DIM + n0 + r) * H_DIM + cgrp * 16;
    const float* uP = up   + ((size_t)e * I_DIM + n0 + r) * H_DIM + cgrp * 16;
    uint32_t dA[4], dG[4], dU[4];
#pragma unroll
    for (int j = 0; j < 4; j++) {
        uint32_t gsw = (uint32_t)((cgrp * 4 + j) ^ (r & 7));
        uint32_t o   = (uint32_t)r * 128 + gsw * 16;
        dA[j] = o; dG[j] = TILE_B + o; dU[j] = 2 * TILE_B + o;
    }

    const int lane = tid & 31, wid = tid >> 5;
    const int wm = wid & 1, wn = wid >> 1;
    const int lr = lane >> 2, lc = lane & 3;
    const int li = lane >> 3, lj = lane & 7;
    const uint32_t j16  = (uint32_t)lj * 16;
    const uint32_t dltA = (uint32_t)(li >> 1) * 16;
    const uint32_t dltB = (uint32_t)(li & 1) * 16;
    uint32_t preA[4], preB[2];
#pragma unroll
    for (int mf = 0; mf < 4; mf++)
        preA[mf] = (uint32_t)(wm * 64 + mf * 16 + (li & 1) * 8 + lj) * 128;
#pragma unroll
    for (int p = 0; p < 2; p++)
        preB[p] = (uint32_t)(wn * 32 + p * 16 + (li >> 1) * 8 + lj) * 128;

    float Cg[4][4][4] = {}, Cu[4][4][4] = {};
    const int NIT = H_DIM / 32;

#pragma unroll
    for (int pit = 0; pit < 2; pit++) {
        uint32_t base = sb + 512 + pit * G1_STAGE;
        int kb = pit * 32;
#pragma unroll
        for (int j = 0; j < 4; j++) {
            cp16(base + dA[j], aP + kb + j * 4);
            cp16(base + dG[j], gP + kb + j * 4);
            cp16(base + dU[j], uP + kb + j * 4);
        }
        CP_COMMIT();
    }

    int buf = 0;
    for (int it = 0; it < NIT; ++it) {
        if (it < NIT - 1) CP_WAIT1(); else CP_WAIT0();
        __syncthreads();

        const uint32_t tA = sb + 512 + buf * G1_STAGE;
        const uint32_t tG = tA + TILE_B;
        const uint32_t tU = tG + TILE_B;
#pragma unroll
        for (int ck = 0; ck < 4; ck++) {
            const uint32_t xc  = (uint32_t)ck * 32;
            const uint32_t swA = (xc | dltA) ^ j16;
            const uint32_t swB = (xc | dltB) ^ j16;
            uint32_t a[4][4];
#pragma unroll
            for (int mf = 0; mf < 4; mf++)
                ldsm4(a[mf], tA + preA[mf] + swA);      // x pre-rounded
            uint32_t bg[2][4], bu[2][4];
#pragma unroll
            for (int p = 0; p < 2; p++) {
                ldsm4(bg[p], tG + preB[p] + swB);
                ldsm4(bu[p], tU + preB[p] + swB);
#pragma unroll
                for (int q = 0; q < 4; q++) {
                    bg[p][q] = rna(bg[p][q]);
                    bu[p][q] = rna(bu[p][q]);
                }
            }
#pragma unroll
            for (int mf = 0; mf < 4; mf++)
#pragma unroll
                for (int nf = 0; nf < 4; nf++) {
                    mma_tf32(Cg[mf][nf], a[mf], &bg[nf >> 1][(nf & 1) * 2]);
                    mma_tf32(Cu[mf][nf], a[mf], &bu[nf >> 1][(nf & 1) * 2]);
                }
        }
        __syncthreads();

        if (it + 2 < NIT) {
            uint32_t base = sb + 512 + ((it + 2) % 3) * G1_STAGE;
            int kb = (it + 2) * 32;
#pragma unroll
            for (int j = 0; j < 4; j++) {
                cp16(base + dA[j], aP + kb + j * 4);
                cp16(base + dG[j], gP + kb + j * 4);
                cp16(base + dU[j], uP + kb + j * 4);
            }
            CP_COMMIT();
        }
        buf = (buf + 1 == 3) ? 0 : buf + 1;
    }

    // epilogue: silu(g)*u*w -> d_act (tf32-rounded)
#pragma unroll
    for (int mf = 0; mf < 4; mf++) {
#pragma unroll
        for (int h = 0; h < 2; h++) {
            int mrow = wm * 64 + mf * 16 + lr + h * 8;
            bool ok  = (m0 + mrow) < cnt;
            int slot = Srow[mrow];
            float w  = ok ? wts[slot] : 0.0f;
            float* dst = d_act + (size_t)slot * I_DIM + n0 + wn * 32 + 2 * lc;
            if (ok) {
#pragma unroll
                for (int nf = 0; nf < 4; nf++) {
                    float g0v = Cg[mf][nf][2 * h],     u0v = Cu[mf][nf][2 * h];
                    float g1v = Cg[mf][nf][2 * h + 1], u1v = Cu[mf][nf][2 * h + 1];
                    float2 o;
                    o.x = rnaf((g0v / (1.0f + __expf(-g0v))) * u0v * w);
                    o.y = rnaf((g1v / (1.0f + __expf(-g1v))) * u1v * w);
                    *(float2*)(dst + nf * 8) = o;
                }
            }
        }
    }
}

// ============================================================================
// GEMM2: down -> red.global.add into out (2 commutative adds/elem, determin.)
// ============================================================================
__global__ __launch_bounds__(256, 2) void k_dn(const float* __restrict__ down,
                                               float* __restrict__ out) {
    extern __shared__ char smem[];
    const int e   = blockIdx.z;
    const int cnt = d_counts[e];
    const int m0  = blockIdx.x * 128;
    if (m0 >= cnt) return;
    const int n0  = blockIdx.y * 128;
    const int tid = threadIdx.x;

    int* Srow = (int*)smem;
    if (tid < 128) {
        int m = m0 + tid;
        Srow[tid] = d_list[e * NSLOT + (m < cnt ? m : m0)];
    }
    __syncthreads();

    const uint32_t sb = smem_u32(smem);

    const int r    = tid >> 1;
    const int cgrp = tid & 1;
    const float* aP = d_act + (size_t)Srow[r] * I_DIM + cgrp * 16;
    const float* bP = down  + ((size_t)e * H_DIM + n0 + r) * I_DIM + cgrp * 16;
    uint32_t dA[4], dB[4];
#pragma unroll
    for (int j = 0; j < 4; j++) {
        uint32_t gsw = (uint32_t)((cgrp * 4 + j) ^ (r & 7));
        uint32_t o   = (uint32_t)r * 128 + gsw * 16;
        dA[j] = o; dB[j] = TILE_B + o;
    }

    const int lane = tid & 31, wid = tid >> 5;
    const int wm = wid & 1, wn = wid >> 1;
    const int lr = lane >> 2, lc = lane & 3;
    const int li = lane >> 3, lj = lane & 7;
    const uint32_t j16  = (uint32_t)lj * 16;
    const uint32_t dltA = (uint32_t)(li >> 1) * 16;
    const uint32_t dltB = (uint32_t)(li & 1) * 16;
    uint32_t preA[4], preB[2];
#pragma unroll
    for (int mf = 0; mf < 4; mf++)
        preA[mf] = (uint32_t)(wm * 64 + mf * 16 + (li & 1) * 8 + lj) * 128;
#pragma unroll
    for (int p = 0; p < 2; p++)
        preB[p] = (uint32_t)(wn * 32 + p * 16 + (li >> 1) * 8 + lj) * 128;

    float C[4][4][4] = {};
    const int NIT = I_DIM / 32;

#pragma unroll
    for (int pit = 0; pit < 2; pit++) {
        uint32_t base = sb + 512 + pit * G2_STAGE;
        int kb = pit * 32;
#pragma unroll
        for (int j = 0; j < 4; j++) {
            cp16(base + dA[j], aP + kb + j * 4);
            cp16(base + dB[j], bP + kb + j * 4);
        }
        CP_COMMIT();
    }

    int buf = 0;
    for (int it = 0; it < NIT; ++it) {
        if (it < NIT - 1) CP_WAIT1(); else CP_WAIT0();
        __syncthreads();

        const uint32_t tA = sb + 512 + buf * G2_STAGE;
        const uint32_t tB = tA + TILE_B;
#pragma unroll
        for (int ck = 0; ck < 4; ck++) {
            const uint32_t xc  = (uint32_t)ck * 32;
            const uint32_t swA = (xc | dltA) ^ j16;
            const uint32_t swB = (xc | dltB) ^ j16;
            uint32_t a[4][4];
#pragma unroll
            for (int mf = 0; mf < 4; mf++)
                ldsm4(a[mf], tA + preA[mf] + swA);      // act pre-rounded
            uint32_t b[2][4];
#pragma unroll
            for (int p = 0; p < 2; p++) {
                ldsm4(b[p], tB + preB[p] + swB);
#pragma unroll
                for (int q = 0; q < 4; q++) b[p][q] = rna(b[p][q]);
            }
#pragma unroll
            for (int mf = 0; mf < 4; mf++)
#pragma unroll
                for (int nf = 0; nf < 4; nf++)
                    mma_tf32(C[mf][nf], a[mf], &b[nf >> 1][(nf & 1) * 2]);
        }
        __syncthreads();

        if (it + 2 < NIT) {
            uint32_t base = sb + 512 + ((it + 2) % 3) * G2_STAGE;
            int kb = (it + 2) * 32;
#pragma unroll
            for (int j = 0; j < 4; j++) {
                cp16(base + dA[j], aP + kb + j * 4);
                cp16(base + dB[j], bP + kb + j * 4);
            }
            CP_COMMIT();
        }
        buf = (buf + 1 == 3) ? 0 : buf + 1;
    }

#pragma unroll
    for (int mf = 0; mf < 4; mf++) {
#pragma unroll
        for (int h = 0; h < 2; h++) {
            int mrow = wm * 64 + mf * 16 + lr + h * 8;
            bool ok  = (m0 + mrow) < cnt;
            int slot = Srow[mrow];
            if (ok) {
                int tok = slot >> 1;
                float* dst = out + (size_t)tok * H_DIM + n0 + wn * 32 + 2 * lc;
#pragma unroll
                for (int nf = 0; nf < 4; nf++) {
                    redadd(dst + nf * 8,     C[mf][nf][2 * h]);
                    redadd(dst + nf * 8 + 1, C[mf][nf][2 * h + 1]);
                }
            }
        }
    }
}

// ---------------- launch -----------------------------------------------------
extern "C" void kernel_launch(void* const* d_in, const int* in_sizes, int n_in,
                              void* d_out, int out_size) {
    const float* x    = (const float*)d_in[0];
    const int*   idx  = (const int*)  d_in[1];
    const float* wts  = (const float*)d_in[2];
    const float* gate = (const float*)d_in[3];
    const float* up   = (const float*)d_in[4];
    const float* down = (const float*)d_in[5];
    float*       out  = (float*)d_out;

    cudaFuncSetAttribute(k_gu, cudaFuncAttributeMaxDynamicSharedMemorySize, G1_SMEM);
    cudaFuncSetAttribute(k_dn, cudaFuncAttributeMaxDynamicSharedMemorySize, G2_SMEM);

    k_prep<<<1, 1024>>>(idx);
    k_route<<<NSLOT / 256, 256>>>(idx);

    float* xr;
    cudaGetSymbolAddress((void**)&xr, d_xr);
    int n4x = T_TOK * H_DIM / 4;
    k_cvtx<<<(n4x + 255) / 256, 256>>>((const float4*)x, (float4*)xr, n4x);
    int n4o = T_TOK * H_DIM / 4;
    k_zero<<<(n4o + 255) / 256, 256>>>((float4*)out, n4o);

    dim3 g1(NSLOT / 128, I_DIM / 128, NEXP);
    k_gu<<<g1, 256, G1_SMEM>>>(gate, up, wts);

    dim3 g2(NSLOT / 128, H_DIM / 128, NEXP);
    k_dn<<<g2, 256, G2_SMEM>>>(down, out);
}

// round 5
// speedup vs baseline: 6.0682x; 1.0724x over previous
#include <cuda_runtime.h>
#include <cstdint>

#define H_DIM 2048
#define I_DIM 1024
#define NEXP  8
#define T_TOK 2048
#define NSLOT 4096   // T_TOK * TOPK

// ---------------- static device scratch -------------------------------------
__device__ int   d_counts[NEXP];
__device__ int   d_list[NEXP * NSLOT];
__device__ int   d_use32;
__device__ float d_act[(size_t)NSLOT * I_DIM];    // 16 MB (tf32-rounded)
__device__ float d_xr[(size_t)T_TOK * H_DIM];     // 16 MB x, tf32-rounded

// ---------------- portable PTX helpers --------------------------------------
__device__ __forceinline__ uint32_t smem_u32(const void* p) {
    uint32_t a;
    asm("{ .reg .u64 t; cvta.to.shared.u64 t, %1; cvt.u32.u64 %0, t; }"
        : "=r"(a) : "l"(p));
    return a;
}
__device__ __forceinline__ void cp16(uint32_t dst, const void* src) {
    asm volatile("cp.async.cg.shared.global [%0], [%1], 16;"
                 :: "r"(dst), "l"(src) : "memory");
}
#define CP_COMMIT() asm volatile("cp.async.commit_group;" ::: "memory")
#define CP_WAIT0()  asm volatile("cp.async.wait_group 0;" ::: "memory")
#define CP_WAIT1()  asm volatile("cp.async.wait_group 1;" ::: "memory")

__device__ __forceinline__ void ldsm4(uint32_t* r, uint32_t addr) {
    asm volatile("ldmatrix.sync.aligned.m8n8.x4.shared.b16 {%0,%1,%2,%3}, [%4];"
                 : "=r"(r[0]), "=r"(r[1]), "=r"(r[2]), "=r"(r[3]) : "r"(addr));
}
__device__ __forceinline__ void mma_tf32(float* c, const uint32_t* a, const uint32_t* b) {
    asm volatile("mma.sync.aligned.m16n8k8.row.col.f32.tf32.tf32.f32 "
                 "{%0,%1,%2,%3}, {%4,%5,%6,%7}, {%8,%9}, {%0,%1,%2,%3};"
                 : "+f"(c[0]), "+f"(c[1]), "+f"(c[2]), "+f"(c[3])
                 : "r"(a[0]), "r"(a[1]), "r"(a[2]), "r"(a[3]),
                   "r"(b[0]), "r"(b[1]));
}
__device__ __forceinline__ uint32_t rna(uint32_t bits) {
    uint32_t u;
    asm("cvt.rna.tf32.f32 %0, %1;" : "=r"(u) : "f"(__uint_as_float(bits)));
    return u;
}
__device__ __forceinline__ float rnaf(float f) {
    uint32_t u;
    asm("cvt.rna.tf32.f32 %0, %1;" : "=r"(u) : "f"(f));
    return __uint_as_float(u);
}
__device__ __forceinline__ void redadd(float* p, float v) {
    asm volatile("red.global.add.f32 [%0], %1;" :: "l"(p), "f"(v) : "memory");
}

// ---------------- routing / prep ---------------------------------------------
__global__ void k_prep(const int* __restrict__ idx32) {
    __shared__ int found;
    if (threadIdx.x == 0) found = 0;
    if (threadIdx.x < NEXP) d_counts[threadIdx.x] = 0;
    __syncthreads();
    int f = 0;
    for (int i = threadIdx.x; i < T_TOK; i += blockDim.x)
        if (idx32[2 * i + 1] != 0) f = 1;
    if (f) atomicOr(&found, 1);
    __syncthreads();
    if (threadIdx.x == 0) d_use32 = found;
}
__global__ void k_route(const int* __restrict__ idx32) {
    int s = blockIdx.x * 256 + threadIdx.x;
    if (s < NSLOT) {
        int e = d_use32 ? idx32[s] : idx32[2 * s];
        int p = atomicAdd(&d_counts[e], 1);
        d_list[e * NSLOT + p] = s;
    }
}
__global__ void k_cvtx(const float4* __restrict__ s, float4* __restrict__ d, int n4) {
    int i = blockIdx.x * blockDim.x + threadIdx.x;
    if (i < n4) {
        float4 v = s[i];
        float4 o;
        o.x = rnaf(v.x); o.y = rnaf(v.y); o.z = rnaf(v.z); o.w = rnaf(v.w);
        d[i] = o;
    }
}
__global__ void k_zero(float4* __restrict__ o, int n4) {
    int i = blockIdx.x * blockDim.x + threadIdx.x;
    if (i < n4) o[i] = make_float4(0.f, 0.f, 0.f, 0.f);
}

// ============================================================================
// Tiling: CTA 128x128, BK=32 (128B rows), swizzle granule g^(row&7).
// ldmatrix lane mapping: li = lane>>3, lj = lane&7.
// A x4: row += (li&1)*8, delta16 = (li>>1)*16
// B x4: row += (li>>1)*8, delta16 = (li&1)*16
// addr = tile + row*128 + (((ck*32)|delta16) ^ (lj*16))
// Single-sync 3-stage ring: at iter top, wait_group(1) + syncthreads, then
// issue cp for it+2 (targets buffer last read at it-1 -> ordered by the sync),
// then compute from buf(it).
// ============================================================================
#define TILE_B   16384
#define G1_STAGE (3 * TILE_B)
#define G1_SMEM  (512 + 3 * G1_STAGE)
#define G2_STAGE (2 * TILE_B)
#define G2_SMEM  (512 + 3 * G2_STAGE)

// ---------------- GEMM1: gate+up, 512 threads, warp tile 32x32 ---------------
__global__ __launch_bounds__(512, 1) void k_gu(
    const float* __restrict__ gate, const float* __restrict__ up,
    const float* __restrict__ wts) {

    extern __shared__ char smem[];
    const int e   = blockIdx.z;
    const int cnt = d_counts[e];
    const int m0  = blockIdx.x * 128;
    if (m0 >= cnt) return;
    const int n0  = blockIdx.y * 128;
    const int tid = threadIdx.x;

    int* Srow = (int*)smem;
    if (tid < 128) {
        int m = m0 + tid;
        Srow[tid] = d_list[e * NSLOT + (m < cnt ? m : m0)];
    }
    __syncthreads();

    const uint32_t sb = smem_u32(smem);

    // cp.async: 512 threads, per tile 1024 granules -> 2 granules/thread
    const int r    = tid >> 2;          // row 0..127
    const int cg2  = tid & 3;           // granule pair
    const float* aP = d_xr + (size_t)(Srow[r] >> 1) * H_DIM + cg2 * 8;
    const float* gP = gate + ((size_t)e * I_DIM + n0 + r) * H_DIM + cg2 * 8;
    const float* uP = up   + ((size_t)e * I_DIM + n0 + r) * H_DIM + cg2 * 8;
    uint32_t dA[2], dG[2], dU[2];
#pragma unroll
    for (int j = 0; j < 2; j++) {
        uint32_t gsw = (uint32_t)((cg2 * 2 + j) ^ (r & 7));
        uint32_t o   = (uint32_t)r * 128 + gsw * 16;
        dA[j] = o; dG[j] = TILE_B + o; dU[j] = 2 * TILE_B + o;
    }

    const int lane = tid & 31, wid = tid >> 5;      // 16 warps
    const int wm = wid & 3, wn = wid >> 2;          // 4M x 4N
    const int lr = lane >> 2, lc = lane & 3;
    const int li = lane >> 3, lj = lane & 7;
    const uint32_t j16  = (uint32_t)lj * 16;
    const uint32_t dltA = (uint32_t)(li >> 1) * 16;
    const uint32_t dltB = (uint32_t)(li & 1) * 16;
    uint32_t preA[2], preB[2];
#pragma unroll
    for (int mf = 0; mf < 2; mf++)
        preA[mf] = (uint32_t)(wm * 32 + mf * 16 + (li & 1) * 8 + lj) * 128;
#pragma unroll
    for (int p = 0; p < 2; p++)
        preB[p] = (uint32_t)(wn * 32 + p * 16 + (li >> 1) * 8 + lj) * 128;

    float Cg[2][4][4] = {}, Cu[2][4][4] = {};
    const int NIT = H_DIM / 32;

#pragma unroll
    for (int pit = 0; pit < 2; pit++) {
        uint32_t base = sb + 512 + pit * G1_STAGE;
        int kb = pit * 32;
#pragma unroll
        for (int j = 0; j < 2; j++) {
            cp16(base + dA[j], aP + kb + j * 4);
            cp16(base + dG[j], gP + kb + j * 4);
            cp16(base + dU[j], uP + kb + j * 4);
        }
        CP_COMMIT();
    }

    int buf = 0;
    for (int it = 0; it < NIT; ++it) {
        if (it < NIT - 1) CP_WAIT1(); else CP_WAIT0();
        __syncthreads();

        if (it + 2 < NIT) {
            uint32_t base = sb + 512 + ((it + 2) % 3) * G1_STAGE;
            int kb = (it + 2) * 32;
#pragma unroll
            for (int j = 0; j < 2; j++) {
                cp16(base + dA[j], aP + kb + j * 4);
                cp16(base + dG[j], gP + kb + j * 4);
                cp16(base + dU[j], uP + kb + j * 4);
            }
            CP_COMMIT();
        }

        const uint32_t tA = sb + 512 + buf * G1_STAGE;
        const uint32_t tG = tA + TILE_B;
        const uint32_t tU = tG + TILE_B;
#pragma unroll
        for (int ck = 0; ck < 4; ck++) {
            const uint32_t xc  = (uint32_t)ck * 32;
            const uint32_t swA = (xc | dltA) ^ j16;
            const uint32_t swB = (xc | dltB) ^ j16;
            uint32_t a[2][4];
#pragma unroll
            for (int mf = 0; mf < 2; mf++)
                ldsm4(a[mf], tA + preA[mf] + swA);       // x pre-rounded
            uint32_t bg[2][4], bu[2][4];
#pragma unroll
            for (int p = 0; p < 2; p++) {
                ldsm4(bg[p], tG + preB[p] + swB);
                ldsm4(bu[p], tU + preB[p] + swB);
#pragma unroll
                for (int q = 0; q < 4; q++) {
                    bg[p][q] = rna(bg[p][q]);
                    bu[p][q] = rna(bu[p][q]);
                }
            }
#pragma unroll
            for (int mf = 0; mf < 2; mf++)
#pragma unroll
                for (int nf = 0; nf < 4; nf++) {
                    mma_tf32(Cg[mf][nf], a[mf], &bg[nf >> 1][(nf & 1) * 2]);
                    mma_tf32(Cu[mf][nf], a[mf], &bu[nf >> 1][(nf & 1) * 2]);
                }
        }
        buf = (buf + 1 == 3) ? 0 : buf + 1;
    }

    // epilogue: silu(g)*u*w -> d_act (tf32-rounded)
#pragma unroll
    for (int mf = 0; mf < 2; mf++) {
#pragma unroll
        for (int h = 0; h < 2; h++) {
            int mrow = wm * 32 + mf * 16 + lr + h * 8;
            bool ok  = (m0 + mrow) < cnt;
            int slot = Srow[mrow];
            float w  = ok ? wts[slot] : 0.0f;
            float* dst = d_act + (size_t)slot * I_DIM + n0 + wn * 32 + 2 * lc;
            if (ok) {
#pragma unroll
                for (int nf = 0; nf < 4; nf++) {
                    float g0v = Cg[mf][nf][2 * h],     u0v = Cu[mf][nf][2 * h];
                    float g1v = Cg[mf][nf][2 * h + 1], u1v = Cu[mf][nf][2 * h + 1];
                    float2 o;
                    o.x = rnaf((g0v / (1.0f + __expf(-g0v))) * u0v * w);
                    o.y = rnaf((g1v / (1.0f + __expf(-g1v))) * u1v * w);
                    *(float2*)(dst + nf * 8) = o;
                }
            }
        }
    }
}

// ---------------- GEMM2: down -> red.global.add into out ---------------------
__global__ __launch_bounds__(256, 2) void k_dn(const float* __restrict__ down,
                                               float* __restrict__ out) {
    extern __shared__ char smem[];
    const int e   = blockIdx.z;
    const int cnt = d_counts[e];
    const int m0  = blockIdx.x * 128;
    if (m0 >= cnt) return;
    const int n0  = blockIdx.y * 128;
    const int tid = threadIdx.x;

    int* Srow = (int*)smem;
    if (tid < 128) {
        int m = m0 + tid;
        Srow[tid] = d_list[e * NSLOT + (m < cnt ? m : m0)];
    }
    __syncthreads();

    const uint32_t sb = smem_u32(smem);

    const int r    = tid >> 1;
    const int cgrp = tid & 1;
    const float* aP = d_act + (size_t)Srow[r] * I_DIM + cgrp * 16;
    const float* bP = down  + ((size_t)e * H_DIM + n0 + r) * I_DIM + cgrp * 16;
    uint32_t dA[4], dB[4];
#pragma unroll
    for (int j = 0; j < 4; j++) {
        uint32_t gsw = (uint32_t)((cgrp * 4 + j) ^ (r & 7));
        uint32_t o   = (uint32_t)r * 128 + gsw * 16;
        dA[j] = o; dB[j] = TILE_B + o;
    }

    const int lane = tid & 31, wid = tid >> 5;
    const int wm = wid & 1, wn = wid >> 1;
    const int lr = lane >> 2, lc = lane & 3;
    const int li = lane >> 3, lj = lane & 7;
    const uint32_t j16  = (uint32_t)lj * 16;
    const uint32_t dltA = (uint32_t)(li >> 1) * 16;
    const uint32_t dltB = (uint32_t)(li & 1) * 16;
    uint32_t preA[4], preB[2];
#pragma unroll
    for (int mf = 0; mf < 4; mf++)
        preA[mf] = (uint32_t)(wm * 64 + mf * 16 + (li & 1) * 8 + lj) * 128;
#pragma unroll
    for (int p = 0; p < 2; p++)
        preB[p] = (uint32_t)(wn * 32 + p * 16 + (li >> 1) * 8 + lj) * 128;

    float C[4][4][4] = {};
    const int NIT = I_DIM / 32;

#pragma unroll
    for (int pit = 0; pit < 2; pit++) {
        uint32_t base = sb + 512 + pit * G2_STAGE;
        int kb = pit * 32;
#pragma unroll
        for (int j = 0; j < 4; j++) {
            cp16(base + dA[j], aP + kb + j * 4);
            cp16(base + dB[j], bP + kb + j * 4);
        }
        CP_COMMIT();
    }

    int buf = 0;
    for (int it = 0; it < NIT; ++it) {
        if (it < NIT - 1) CP_WAIT1(); else CP_WAIT0();
        __syncthreads();

        if (it + 2 < NIT) {
            uint32_t base = sb + 512 + ((it + 2) % 3) * G2_STAGE;
            int kb = (it + 2) * 32;
#pragma unroll
            for (int j = 0; j < 4; j++) {
                cp16(base + dA[j], aP + kb + j * 4);
                cp16(base + dB[j], bP + kb + j * 4);
            }
            CP_COMMIT();
        }

        const uint32_t tA = sb + 512 + buf * G2_STAGE;
        const uint32_t tB = tA + TILE_B;
#pragma unroll
        for (int ck = 0; ck < 4; ck++) {
            const uint32_t xc  = (uint32_t)ck * 32;
            const uint32_t swA = (xc | dltA) ^ j16;
            const uint32_t swB = (xc | dltB) ^ j16;
            uint32_t a[4][4];
#pragma unroll
            for (int mf = 0; mf < 4; mf++)
                ldsm4(a[mf], tA + preA[mf] + swA);       // act pre-rounded
            uint32_t b[2][4];
#pragma unroll
            for (int p = 0; p < 2; p++) {
                ldsm4(b[p], tB + preB[p] + swB);
#pragma unroll
                for (int q = 0; q < 4; q++) b[p][q] = rna(b[p][q]);
            }
#pragma unroll
            for (int mf = 0; mf < 4; mf++)
#pragma unroll
                for (int nf = 0; nf < 4; nf++)
                    mma_tf32(C[mf][nf], a[mf], &b[nf >> 1][(nf & 1) * 2]);
        }
        buf = (buf + 1 == 3) ? 0 : buf + 1;
    }

#pragma unroll
    for (int mf = 0; mf < 4; mf++) {
#pragma unroll
        for (int h = 0; h < 2; h++) {
            int mrow = wm * 64 + mf * 16 + lr + h * 8;
            bool ok  = (m0 + mrow) < cnt;
            int slot = Srow[mrow];
            if (ok) {
                int tok = slot >> 1;
                float* dst = out + (size_t)tok * H_DIM + n0 + wn * 32 + 2 * lc;
#pragma unroll
                for (int nf = 0; nf < 4; nf++) {
                    redadd(dst + nf * 8,     C[mf][nf][2 * h]);
                    redadd(dst + nf * 8 + 1, C[mf][nf][2 * h + 1]);
                }
            }
        }
    }
}

// ---------------- launch -----------------------------------------------------
extern "C" void kernel_launch(void* const* d_in, const int* in_sizes, int n_in,
                              void* d_out, int out_size) {
    const float* x    = (const float*)d_in[0];
    const int*   idx  = (const int*)  d_in[1];
    const float* wts  = (const float*)d_in[2];
    const float* gate = (const float*)d_in[3];
    const float* up   = (const float*)d_in[4];
    const float* down = (const float*)d_in[5];
    float*       out  = (float*)d_out;

    cudaFuncSetAttribute(k_gu, cudaFuncAttributeMaxDynamicSharedMemorySize, G1_SMEM);
    cudaFuncSetAttribute(k_dn, cudaFuncAttributeMaxDynamicSharedMemorySize, G2_SMEM);

    k_prep<<<1, 1024>>>(idx);
    k_route<<<NSLOT / 256, 256>>>(idx);

    float* xr;
    cudaGetSymbolAddress((void**)&xr, d_xr);
    int n4x = T_TOK * H_DIM / 4;
    k_cvtx<<<(n4x + 255) / 256, 256>>>((const float4*)x, (float4*)xr, n4x);
    k_zero<<<(n4x + 255) / 256, 256>>>((float4*)out, n4x);

    dim3 g1(NSLOT / 128, I_DIM / 128, NEXP);
    k_gu<<<g1, 512, G1_SMEM>>>(gate, up, wts);

    dim3 g2(NSLOT / 128, H_DIM / 128, NEXP);
    k_dn<<<g2, 256, G2_SMEM>>>(down, out);
}